// round 7
// baseline (speedup 1.0000x reference)
#include <cuda_runtime.h>
#include <cuda_bf16.h>

#define NMAX 50000
#define EMAX 800000
#define F 128
#define EFD 6

#define PREP_BLOCKS 592
#define PREP_T 512

// ---- packed dual-fp32 ops (Blackwell f32x2) --------------------------------
#define PACK_F32X2(d, a, b) \
    asm("mov.b64 %0, {%1, %2};" : "=l"(d) : "f"(a), "f"(b))
#define FMA_F32X2(d, a, b, c) \
    asm("fma.rn.f32x2 %0, %1, %2, %3;" : "=l"(d) : "l"(a), "l"(b), "l"(c))
#define UNPACK_F32X2(lo, hi, v) \
    asm("mov.b64 {%0, %1}, %2;" : "=f"(lo), "=f"(hi) : "l"(v))

// ---------------- device scratch ----------------
__device__ int      g_is64;
__device__ int      g_counts[NMAX];
__device__ int      g_cursor[NMAX];
__device__ int      g_rowptr[NMAX + 1];
__device__ int      g_src[EMAX];
__device__ int      g_dst[EMAX];
__device__ int2     g_edges[EMAX];
__device__ int      g_blocksum[256];
__device__ int      g_blockoff[256];
__device__ int      g_bar[5];
__device__ unsigned g_work;              // work-stealing counter for fused

// ---------------- software grid barrier -------------------------------------
__device__ __forceinline__ void grid_barrier(int id) {
    __syncthreads();
    if (threadIdx.x == 0) {
        __threadfence();
        atomicAdd(&g_bar[id], 1);
        const volatile int* vb = g_bar;
        while (vb[id] < PREP_BLOCKS) { }
        __threadfence();
    }
    __syncthreads();
}

// ---------------- fused prep: zero+detect | hist | scan | scatter ------------
__global__ void __launch_bounds__(PREP_T, 4)
k_prep(const void* __restrict__ ei, int N, int E) {
    const int tid  = blockIdx.x * PREP_T + threadIdx.x;
    const int nth  = PREP_BLOCKS * PREP_T;
    const int lane = threadIdx.x & 31;
    const int T    = (N + 255) >> 8;

    if (blockIdx.x == 0 && threadIdx.x == 0) {
        const long long* p = (const long long*)ei;
        int ok = 1;
        int lim = E < 128 ? E : 128;
        for (int j = 0; j < lim; j++) {
            long long v = p[j];
            if (v < 0 || v >= (long long)N) { ok = 0; break; }
        }
        g_is64 = ok;
        atomicExch(&g_bar[4], 0);
        atomicExch(&g_work, 0u);          // reset fused work counter
    }
    for (int i = tid; i < N; i += nth) g_counts[i] = 0;
    grid_barrier(0);

    const int is64 = __ldcg(&g_is64);
    if (is64) {
        const longlong2* p = (const longlong2*)ei;
        for (int e = tid; e < E; e += nth) {
            longlong2 v = p[e];
            int s = (int)v.x, d = (int)v.y;
            g_src[e] = s; g_dst[e] = d;
            atomicAdd(&g_counts[d], 1);
        }
    } else {
        const int2* p = (const int2*)ei;
        for (int e = tid; e < E; e += nth) {
            int2 v = p[e];
            g_src[e] = v.x; g_dst[e] = v.y;
            atomicAdd(&g_counts[v.y], 1);
        }
    }
    grid_barrier(1);
    if (blockIdx.x == 0 && threadIdx.x == 0) atomicExch(&g_bar[0], 0);

    {
        int gw = tid >> 5;
        int nw = nth >> 5;
        for (int t = gw; t < T; t += nw) {
            int base = t << 8;
            int v[8]; int s = 0;
            #pragma unroll
            for (int j = 0; j < 8; j++) {
                int idx = base + lane * 8 + j;
                int c = (idx < N) ? __ldcg(&g_counts[idx]) : 0;
                v[j] = s; s += c;
            }
            int x = s;
            #pragma unroll
            for (int o = 1; o < 32; o <<= 1) {
                int y = __shfl_up_sync(0xffffffffu, x, o);
                if (lane >= o) x += y;
            }
            int excl = x - s;
            #pragma unroll
            for (int j = 0; j < 8; j++) {
                int idx = base + lane * 8 + j;
                if (idx < N) g_rowptr[idx] = excl + v[j];
            }
            if (lane == 31) g_blocksum[t] = x;
        }
    }
    grid_barrier(2);
    if (blockIdx.x == 0 && threadIdx.x == 0) atomicExch(&g_bar[1], 0);

    if (blockIdx.x == 0 && threadIdx.x < 32) {
        int vals[7]; int s = 0;
        #pragma unroll
        for (int j = 0; j < 7; j++) {
            int idx = lane * 7 + j;
            int v = (idx < T) ? __ldcg(&g_blocksum[idx]) : 0;
            vals[j] = s; s += v;
        }
        int x = s;
        #pragma unroll
        for (int o = 1; o < 32; o <<= 1) {
            int y = __shfl_up_sync(0xffffffffu, x, o);
            if (lane >= o) x += y;
        }
        int excl = x - s;
        #pragma unroll
        for (int j = 0; j < 7; j++) {
            int idx = lane * 7 + j;
            if (idx < T) g_blockoff[idx] = excl + vals[j];
        }
        if (lane == 31) g_rowptr[N] = x;
    }
    grid_barrier(3);
    if (blockIdx.x == 0 && threadIdx.x == 0) atomicExch(&g_bar[2], 0);

    for (int i = tid; i < N; i += nth) {
        int r = __ldcg(&g_rowptr[i]) + __ldcg(&g_blockoff[i >> 8]);
        g_rowptr[i] = r;
        g_cursor[i] = r;
    }
    grid_barrier(4);
    if (blockIdx.x == 0 && threadIdx.x == 0) atomicExch(&g_bar[3], 0);

    for (int e0 = tid * 4; e0 < E; e0 += nth * 4) {
        int d[4], s[4];
        #pragma unroll
        for (int j = 0; j < 4; j++) {
            int e = e0 + j;
            if (e < E) { d[j] = __ldcg(&g_dst[e]); s[j] = __ldcg(&g_src[e]); }
        }
        #pragma unroll
        for (int j = 0; j < 4; j++) {
            int e = e0 + j;
            if (e < E) {
                int p = atomicAdd(&g_cursor[d[j]], 1);
                g_edges[p] = make_int2(s[j], e);
            }
        }
    }
}

// ---------------- fused gather + GEMM: persistent warps, 8 rows/warp ---------
#define FT 128
#define FW 4                 // warps per block
#define FRPW 8               // nodes per warp-group
// staging: per warp 8 rows x 128 k x 8B (duplicated pairs) = 8KB

__global__ void __launch_bounds__(FT, 6)
k_fused(const float4* __restrict__ X4, const float* __restrict__ eF,
        const float4* __restrict__ W4, const float4* __restrict__ b4p,
        const float4* __restrict__ We4, const float4* __restrict__ be4,
        float4* __restrict__ out4, int N, int nGroups) {
    __shared__ float4 xsd[FW][FRPW * 64];   // 32 KB: (x,x,x',x') pairs

    int tid = threadIdx.x, warp = tid >> 5, lane = tid & 31;
    float4* xw = xsd[warp];

    for (;;) {
        // ---- per-warp work stealing
        unsigned g;
        if (lane == 0) g = atomicAdd(&g_work, 1u);
        g = __shfl_sync(0xffffffffu, g, 0);
        if (g >= (unsigned)nGroups) break;
        int row0 = (int)g * FRPW;

        float ae[FRPW];
        int   degv[FRPW];

        // ---- gather phase: sum X[src] per node, store duplicated pairs
        #pragma unroll
        for (int r = 0; r < FRPW; r++) {
            float4 acc = make_float4(0.f, 0.f, 0.f, 0.f);
            float a = 0.f;
            int deg = 0;
            int row = row0 + r;
            if (row < N) {
                int s0 = __ldcg(&g_rowptr[row]);
                int s1 = __ldcg(&g_rowptr[row + 1]);
                deg = s1 - s0;
                for (int base = s0; base < s1; base += 32) {
                    int cnt = s1 - base; if (cnt > 32) cnt = 32;
                    int2 se = __ldcg(&g_edges[base + (lane < cnt ? lane : 0)]);
                    for (int j = 0; j < cnt; j += 8) {
                        #pragma unroll
                        for (int u = 0; u < 8; u++) {
                            if (j + u < cnt) {  // uniform across warp
                                int sj = __shfl_sync(0xffffffffu, se.x, j + u);
                                int ej = __shfl_sync(0xffffffffu, se.y, j + u);
                                float4 xv = __ldcg(&X4[(long)sj * 32 + lane]);
                                acc.x += xv.x; acc.y += xv.y;
                                acc.z += xv.z; acc.w += xv.w;
                                if (lane < EFD) a += __ldcg(&eF[(long)ej * EFD + lane]);
                            }
                        }
                    }
                }
            }
            // duplicated-pair staging: k=4*lane..4*lane+3 -> float4 idx r*64+2*lane(+1)
            xw[r * 64 + 2 * lane]     = make_float4(acc.x, acc.x, acc.y, acc.y);
            xw[r * 64 + 2 * lane + 1] = make_float4(acc.z, acc.z, acc.w, acc.w);
            ae[r] = a;
            degv[r] = deg;
        }
        __syncwarp();

        // ---- GEMM phase: f32x2, W via L1, x via broadcast LDS of dup pairs
        unsigned long long a01[FRPW], a23[FRPW];
        #pragma unroll
        for (int r = 0; r < FRPW; r++) { a01[r] = 0ULL; a23[r] = 0ULL; }

        for (int kb = 0; kb < F; kb += 4) {
            unsigned long long w01[4], w23[4];
            #pragma unroll
            for (int kk = 0; kk < 4; kk++) {
                float4 w4 = __ldg(&W4[(kb + kk) * 32 + lane]);
                PACK_F32X2(w01[kk], w4.x, w4.y);
                PACK_F32X2(w23[kk], w4.z, w4.w);
            }
            #pragma unroll
            for (int r = 0; r < FRPW; r++) {
                // two 16B broadcast loads give (x_k,x_k,x_k+1,x_k+1) pairs
                ulonglong2 xa = *(const ulonglong2*)&xw[r * 64 + (kb >> 1)];
                ulonglong2 xb = *(const ulonglong2*)&xw[r * 64 + (kb >> 1) + 1];
                FMA_F32X2(a01[r], xa.x, w01[0], a01[r]);
                FMA_F32X2(a23[r], xa.x, w23[0], a23[r]);
                FMA_F32X2(a01[r], xa.y, w01[1], a01[r]);
                FMA_F32X2(a23[r], xa.y, w23[1], a23[r]);
                FMA_F32X2(a01[r], xb.x, w01[2], a01[r]);
                FMA_F32X2(a23[r], xb.x, w23[2], a23[r]);
                FMA_F32X2(a01[r], xb.y, w01[3], a01[r]);
                FMA_F32X2(a23[r], xb.y, w23[3], a23[r]);
            }
        }

        // ---- epilogue
        float4 bb = __ldg(&b4p[lane]);
        float4 be = __ldg(&be4[lane]);
        float4 bs = make_float4(bb.x + be.x, bb.y + be.y,
                                bb.z + be.z, bb.w + be.w);
        #pragma unroll
        for (int r = 0; r < FRPW; r++) {
            int row = row0 + r;
            if (row >= N) break;
            float deg = (float)degv[r];
            float4 o;
            UNPACK_F32X2(o.x, o.y, a01[r]);
            UNPACK_F32X2(o.z, o.w, a23[r]);
            o.x = fmaf(deg, bs.x, o.x);
            o.y = fmaf(deg, bs.y, o.y);
            o.z = fmaf(deg, bs.z, o.z);
            o.w = fmaf(deg, bs.w, o.w);
            #pragma unroll
            for (int k = 0; k < EFD; k++) {
                float ek = __shfl_sync(0xffffffffu, ae[r], k);
                float4 w4 = __ldg(&We4[k * 32 + lane]);
                o.x = fmaf(ek, w4.x, o.x);
                o.y = fmaf(ek, w4.y, o.y);
                o.z = fmaf(ek, w4.z, o.z);
                o.w = fmaf(ek, w4.w, o.w);
            }
            o.x = fmaxf(o.x, 0.f); o.y = fmaxf(o.y, 0.f);
            o.z = fmaxf(o.z, 0.f); o.w = fmaxf(o.w, 0.f);
            out4[(long)row * 32 + lane] = o;
        }
        __syncwarp();
    }
}

// ---------------------------------------------------------------------------
extern "C" void kernel_launch(void* const* d_in, const int* in_sizes, int n_in,
                              void* d_out, int out_size) {
    const float* X  = (const float*)d_in[0];
    const void*  EI = d_in[1];
    const float* EF = (const float*)d_in[2];
    const float* W  = (const float*)d_in[3];
    const float* b  = (const float*)d_in[4];
    const float* We = (const float*)d_in[5];
    const float* be = (const float*)d_in[6];
    float* out = (float*)d_out;

    int N = in_sizes[0] / F;
    int E = in_sizes[2] / EFD;
    int nGroups = (N + FRPW - 1) / FRPW;

    k_prep<<<PREP_BLOCKS, PREP_T>>>(EI, N, E);
    k_fused<<<148 * 6, FT>>>((const float4*)X, EF, (const float4*)W,
                             (const float4*)b, (const float4*)We,
                             (const float4*)be, (float4*)out, N, nGroups);
}